// round 2
// baseline (speedup 1.0000x reference)
#include <cuda_runtime.h>
#include <math.h>

#define NN 20000
#define EE 320000
#define ETOT (EE + NN)

// ---------------- device scratch (no allocations allowed) ----------------
__device__ __align__(16) float g_hA[NN * 64];
__device__ __align__(16) float g_hB[NN * 64];
__device__ __align__(16) float g_hproj[NN * 256];
__device__ __align__(16) float g_asrc[NN * 4];
__device__ __align__(16) float g_adst[NN * 4];
__device__ int g_deg[NN];
__device__ int g_rowptr[NN + 1];
__device__ int g_cursor[NN];
__device__ int g_esrc[ETOT];
__device__ int g_is64;

// ---------------- edge dtype detection (int64 vs int32) ----------------
__global__ void detect_kernel(const void* edges) {
    const long long* p = (const long long*)edges;
    int lane = threadIdx.x;
    bool ok = true;
    for (int i = lane; i < 512; i += 32) {
        long long v = p[i];
        if (v < 0 || v >= NN) ok = false;
    }
    unsigned m = __ballot_sync(0xffffffffu, ok);
    if (lane == 0) g_is64 = (m == 0xffffffffu) ? 1 : 0;
}

// ---------------- encoder MLP: x[N,8] -> 32 -> 64, ELU ----------------
__global__ void encode_kernel(const float* __restrict__ x,
                              const float* __restrict__ W1, const float* __restrict__ b1,
                              const float* __restrict__ W2, const float* __restrict__ b2) {
    __shared__ float sW1[8 * 32], sb1[32], sW2[32 * 64], sb2[64];
    for (int i = threadIdx.x; i < 256; i += blockDim.x) sW1[i] = W1[i];
    for (int i = threadIdx.x; i < 32; i += blockDim.x) sb1[i] = b1[i];
    for (int i = threadIdx.x; i < 2048; i += blockDim.x) sW2[i] = W2[i];
    for (int i = threadIdx.x; i < 64; i += blockDim.x) sb2[i] = b2[i];
    __syncthreads();
    int v = blockIdx.x * blockDim.x + threadIdx.x;
    if (v >= NN) return;
    float xr[8];
#pragma unroll
    for (int k = 0; k < 8; k++) xr[k] = x[v * 8 + k];
    float t[32];
#pragma unroll
    for (int j = 0; j < 32; j++) {
        float s = sb1[j];
#pragma unroll
        for (int k = 0; k < 8; k++) s = fmaf(xr[k], sW1[k * 32 + j], s);
        t[j] = (s > 0.f) ? s : expm1f(s);
    }
    for (int j = 0; j < 64; j++) {
        float s = sb2[j];
#pragma unroll
        for (int k = 0; k < 32; k++) s = fmaf(t[k], sW2[k * 64 + j], s);
        g_hA[v * 64 + j] = (s > 0.f) ? s : expm1f(s);
    }
}

// ---------------- CSR build ----------------
__global__ void initdeg_kernel() {
    int i = blockIdx.x * blockDim.x + threadIdx.x;
    if (i < NN) g_deg[i] = 1;  // self-loop
}

__global__ void hist_kernel(const void* edges) {
    int e = blockIdx.x * blockDim.x + threadIdx.x;
    if (e >= EE) return;
    int d = g_is64 ? (int)((const long long*)edges)[EE + e]
                   : ((const int*)edges)[EE + e];
    atomicAdd(&g_deg[d], 1);
}

__global__ void scan_kernel() {
    __shared__ int sums[1024];
    int t = threadIdx.x;
    constexpr int CH = 20;  // 1024*20 >= 20000
    int base = t * CH;
    int local[CH];
    int s = 0;
#pragma unroll
    for (int i = 0; i < CH; i++) {
        int v = (base + i < NN) ? g_deg[base + i] : 0;
        local[i] = s;
        s += v;
    }
    sums[t] = s;
    __syncthreads();
    for (int off = 1; off < 1024; off <<= 1) {
        int v = (t >= off) ? sums[t - off] : 0;
        __syncthreads();
        sums[t] += v;
        __syncthreads();
    }
    int prefix = (t > 0) ? sums[t - 1] : 0;
#pragma unroll
    for (int i = 0; i < CH; i++) {
        if (base + i < NN) {
            g_rowptr[base + i] = prefix + local[i];
            g_cursor[base + i] = prefix + local[i];
        }
    }
    if (t == 1023) g_rowptr[NN] = sums[1023];
}

__global__ void scatter_kernel(const void* edges) {
    int e = blockIdx.x * blockDim.x + threadIdx.x;
    if (e < EE) {
        int s, d;
        if (g_is64) {
            s = (int)((const long long*)edges)[e];
            d = (int)((const long long*)edges)[EE + e];
        } else {
            s = ((const int*)edges)[e];
            d = ((const int*)edges)[EE + e];
        }
        int pos = atomicAdd(&g_cursor[d], 1);
        g_esrc[pos] = s;
    } else if (e < EE + NN) {
        int v = e - EE;
        int pos = atomicAdd(&g_cursor[v], 1);
        g_esrc[pos] = v;
    }
}

// ---- projection GEMM + fused attention scores ----
// hproj = x_in[N,64] @ W[64,256]; per 64x64 tile (blockIdx.y = head h),
// also computes a_src[n,h] = dot(hproj[n, h*64:(h+1)*64], att_src[h]) and same for a_dst.
__global__ void gemm_kernel(const float* __restrict__ B,
                            const float* __restrict__ as_, const float* __restrict__ ad_,
                            int srcA) {
    const float* A = srcA ? g_hA : g_hB;
    __shared__ __align__(16) float As[64 * 65];
    __shared__ __align__(16) float Bs[64 * 68];
    int rowBase = blockIdx.x * 64;
    int colBase = blockIdx.y * 64;  // == head h * 64
    for (int i = threadIdx.x; i < 4096; i += 256) {
        int r = i >> 6, k = i & 63;
        int gr = rowBase + r;
        As[r * 65 + k] = (gr < NN) ? A[gr * 64 + k] : 0.f;
        Bs[r * 68 + k] = B[r * 256 + colBase + k];  // r = K index
    }
    __syncthreads();
    int tx = threadIdx.x & 15, ty = threadIdx.x >> 4;
    int r0 = ty * 4, c0 = tx * 4;
    float acc[4][4] = {};
#pragma unroll
    for (int k = 0; k < 64; k++) {
        float a[4];
#pragma unroll
        for (int i = 0; i < 4; i++) a[i] = As[(r0 + i) * 65 + k];
        float4 bv = *reinterpret_cast<const float4*>(&Bs[k * 68 + c0]);
        float b[4] = {bv.x, bv.y, bv.z, bv.w};
#pragma unroll
        for (int i = 0; i < 4; i++)
#pragma unroll
            for (int j = 0; j < 4; j++) acc[i][j] = fmaf(a[i], b[j], acc[i][j]);
    }
    // store hproj tile
#pragma unroll
    for (int i = 0; i < 4; i++) {
        int gr = rowBase + r0 + i;
        if (gr < NN) {
#pragma unroll
            for (int j = 0; j < 4; j++)
                g_hproj[(size_t)gr * 256 + colBase + c0 + j] = acc[i][j];
        }
    }
    // fused attention dots: att vectors flat index = colBase + local channel
    float av[4], dv[4];
#pragma unroll
    for (int j = 0; j < 4; j++) {
        av[j] = as_[colBase + c0 + j];
        dv[j] = ad_[colBase + c0 + j];
    }
#pragma unroll
    for (int i = 0; i < 4; i++) {
        float sa = acc[i][0] * av[0] + acc[i][1] * av[1] + acc[i][2] * av[2] + acc[i][3] * av[3];
        float sd = acc[i][0] * dv[0] + acc[i][1] * dv[1] + acc[i][2] * dv[2] + acc[i][3] * dv[3];
#pragma unroll
        for (int off = 8; off > 0; off >>= 1) {
            sa += __shfl_down_sync(0xffffffffu, sa, off, 16);
            sd += __shfl_down_sync(0xffffffffu, sd, off, 16);
        }
        int gr = rowBase + r0 + i;
        if (tx == 0 && gr < NN) {
            g_asrc[gr * 4 + blockIdx.y] = sa;
            g_adst[gr * 4 + blockIdx.y] = sd;
        }
    }
}

// ---------------- GAT edge pass: softmax + aggregate + head-mean + bias + residual ----
__device__ __forceinline__ float lrelu(float x) { return fmaxf(x, 0.2f * x); }

__global__ void gat_edge_kernel(const float* __restrict__ bias, int srcA) {
    const float* xin = srcA ? g_hA : g_hB;
    float* xout = srcA ? g_hB : g_hA;
    int warp = (blockIdx.x * blockDim.x + threadIdx.x) >> 5;
    int lane = threadIdx.x & 31;
    if (warp >= NN) return;
    int beg = g_rowptr[warp], end = g_rowptr[warp + 1];
    float4 adv = *reinterpret_cast<const float4*>(&g_adst[warp * 4]);

    // pass 1: online softmax stats (max + rescaled sum) per head
    float m0 = -1e30f, m1 = -1e30f, m2 = -1e30f, m3 = -1e30f;
    float s0 = 0.f, s1 = 0.f, s2 = 0.f, s3 = 0.f;
    for (int e = beg + lane; e < end; e += 32) {
        int s = g_esrc[e];
        float4 av = *reinterpret_cast<const float4*>(&g_asrc[s * 4]);
        float v0 = lrelu(av.x + adv.x);
        float v1 = lrelu(av.y + adv.y);
        float v2 = lrelu(av.z + adv.z);
        float v3 = lrelu(av.w + adv.w);
        if (v0 > m0) { s0 = s0 * __expf(m0 - v0) + 1.f; m0 = v0; } else s0 += __expf(v0 - m0);
        if (v1 > m1) { s1 = s1 * __expf(m1 - v1) + 1.f; m1 = v1; } else s1 += __expf(v1 - m1);
        if (v2 > m2) { s2 = s2 * __expf(m2 - v2) + 1.f; m2 = v2; } else s2 += __expf(v2 - m2);
        if (v3 > m3) { s3 = s3 * __expf(m3 - v3) + 1.f; m3 = v3; } else s3 += __expf(v3 - m3);
    }
#pragma unroll
    for (int o = 16; o > 0; o >>= 1) {
        float mo, so, mn;
        mo = __shfl_xor_sync(0xffffffffu, m0, o); so = __shfl_xor_sync(0xffffffffu, s0, o);
        mn = fmaxf(m0, mo); s0 = s0 * __expf(m0 - mn) + so * __expf(mo - mn); m0 = mn;
        mo = __shfl_xor_sync(0xffffffffu, m1, o); so = __shfl_xor_sync(0xffffffffu, s1, o);
        mn = fmaxf(m1, mo); s1 = s1 * __expf(m1 - mn) + so * __expf(mo - mn); m1 = mn;
        mo = __shfl_xor_sync(0xffffffffu, m2, o); so = __shfl_xor_sync(0xffffffffu, s2, o);
        mn = fmaxf(m2, mo); s2 = s2 * __expf(m2 - mn) + so * __expf(mo - mn); m2 = mn;
        mo = __shfl_xor_sync(0xffffffffu, m3, o); so = __shfl_xor_sync(0xffffffffu, s3, o);
        mn = fmaxf(m3, mo); s3 = s3 * __expf(m3 - mn) + so * __expf(mo - mn); m3 = mn;
    }
    float i0 = 1.f / (s0 + 1e-16f);
    float i1 = 1.f / (s1 + 1e-16f);
    float i2 = 1.f / (s2 + 1e-16f);
    float i3 = 1.f / (s3 + 1e-16f);

    // pass 2: weighted aggregation; lane owns channels (lane, lane+32)
    float acc0a = 0.f, acc0b = 0.f, acc1a = 0.f, acc1b = 0.f;
    for (int base = beg; base < end; base += 32) {
        int cnt = min(32, end - base);
        int s = 0;
        float w0 = 0.f, w1 = 0.f, w2 = 0.f, w3 = 0.f;
        if (lane < cnt) {
            s = g_esrc[base + lane];
            float4 av = *reinterpret_cast<const float4*>(&g_asrc[s * 4]);
            w0 = __expf(lrelu(av.x + adv.x) - m0) * i0;
            w1 = __expf(lrelu(av.y + adv.y) - m1) * i1;
            w2 = __expf(lrelu(av.z + adv.z) - m2) * i2;
            w3 = __expf(lrelu(av.w + adv.w) - m3) * i3;
        }
        for (int j = 0; j < cnt; j++) {
            int sj = __shfl_sync(0xffffffffu, s, j);
            float w0j = __shfl_sync(0xffffffffu, w0, j);
            float w1j = __shfl_sync(0xffffffffu, w1, j);
            float w2j = __shfl_sync(0xffffffffu, w2, j);
            float w3j = __shfl_sync(0xffffffffu, w3, j);
            const float* hp = g_hproj + (size_t)sj * 256;
            acc0a = fmaf(w0j, __ldg(hp + lane), acc0a);
            acc0b = fmaf(w1j, __ldg(hp + 64 + lane), acc0b);
            acc0a = fmaf(w2j, __ldg(hp + 128 + lane), acc0a);
            acc0b = fmaf(w3j, __ldg(hp + 192 + lane), acc0b);
            acc1a = fmaf(w0j, __ldg(hp + 32 + lane), acc1a);
            acc1b = fmaf(w1j, __ldg(hp + 96 + lane), acc1b);
            acc1a = fmaf(w2j, __ldg(hp + 160 + lane), acc1a);
            acc1b = fmaf(w3j, __ldg(hp + 224 + lane), acc1b);
        }
    }
    xout[warp * 64 + lane] = (acc0a + acc0b) * 0.25f + bias[lane] + xin[warp * 64 + lane];
    xout[warp * 64 + 32 + lane] = (acc1a + acc1b) * 0.25f + bias[32 + lane] + xin[warp * 64 + 32 + lane];
}

// ---------------- output MLP: h3[N,64] -> 64 -> 32 -> 8 ----------------
__global__ void __launch_bounds__(64) outmlp_kernel(
    const float* __restrict__ W1, const float* __restrict__ b1,
    const float* __restrict__ W2, const float* __restrict__ b2,
    const float* __restrict__ W3, const float* __restrict__ b3,
    float* __restrict__ out) {
    __shared__ float sW1[64 * 64], sb1[64], sW2[64 * 32], sb2[32], sW3[32 * 8], sb3[8];
    __shared__ float sh[64 * 65];
    int tid = threadIdx.x;
    for (int i = tid; i < 4096; i += 64) sW1[i] = W1[i];
    if (tid < 64) sb1[tid] = b1[tid];
    for (int i = tid; i < 2048; i += 64) sW2[i] = W2[i];
    if (tid < 32) sb2[tid] = b2[tid];
    for (int i = tid; i < 256; i += 64) sW3[i] = W3[i];
    if (tid < 8) sb3[tid] = b3[tid];
    int vbase = blockIdx.x * 64;
    for (int i = tid; i < 64 * 64; i += 64) {
        int r = i >> 6, c = i & 63;
        int v = vbase + r;
        sh[r * 65 + c] = (v < NN) ? g_hB[v * 64 + c] : 0.f;
    }
    __syncthreads();
    int v = vbase + tid;
    if (v >= NN) return;
    const float* hr = &sh[tid * 65];
    float t1[64];
    for (int j = 0; j < 64; j++) {
        float s = sb1[j];
#pragma unroll
        for (int k = 0; k < 64; k++) s = fmaf(hr[k], sW1[k * 64 + j], s);
        t1[j] = (s > 0.f) ? s : expm1f(s);
    }
    float t2[32];
    for (int j = 0; j < 32; j++) {
        float s = sb2[j];
#pragma unroll
        for (int k = 0; k < 64; k++) s = fmaf(t1[k], sW2[k * 32 + j], s);
        t2[j] = (s > 0.f) ? s : expm1f(s);
    }
    for (int j = 0; j < 8; j++) {
        float s = sb3[j];
#pragma unroll
        for (int k = 0; k < 32; k++) s = fmaf(t2[k], sW3[k * 8 + j], s);
        out[v * 8 + j] = s;
    }
}

// ---------------- launch ----------------
extern "C" void kernel_launch(void* const* d_in, const int* in_sizes, int n_in,
                              void* d_out, int out_size) {
    const float* x = (const float*)d_in[0];
    const void* edges = d_in[1];
    const float* Wenc1 = (const float*)d_in[2];
    const float* benc1 = (const float*)d_in[3];
    const float* Wenc2 = (const float*)d_in[4];
    const float* benc2 = (const float*)d_in[5];
    const float* Wg[3] = {(const float*)d_in[6], (const float*)d_in[10], (const float*)d_in[14]};
    const float* as_[3] = {(const float*)d_in[7], (const float*)d_in[11], (const float*)d_in[15]};
    const float* ad_[3] = {(const float*)d_in[8], (const float*)d_in[12], (const float*)d_in[16]};
    const float* bg[3] = {(const float*)d_in[9], (const float*)d_in[13], (const float*)d_in[17]};
    const float* Wo1 = (const float*)d_in[18];
    const float* bo1 = (const float*)d_in[19];
    const float* Wo2 = (const float*)d_in[20];
    const float* bo2 = (const float*)d_in[21];
    const float* Wo3 = (const float*)d_in[22];
    const float* bo3 = (const float*)d_in[23];
    float* out = (float*)d_out;

    detect_kernel<<<1, 32>>>(edges);
    encode_kernel<<<(NN + 255) / 256, 256>>>(x, Wenc1, benc1, Wenc2, benc2);
    initdeg_kernel<<<(NN + 255) / 256, 256>>>();
    hist_kernel<<<(EE + 255) / 256, 256>>>(edges);
    scan_kernel<<<1, 1024>>>();
    scatter_kernel<<<(EE + NN + 255) / 256, 256>>>(edges);

    // layer l: input in g_hA if srcA, output flips; encode wrote g_hA.
    int srcA = 1;
    for (int l = 0; l < 3; l++) {
        gemm_kernel<<<dim3(313, 4), 256>>>(Wg[l], as_[l], ad_[l], srcA);
        gat_edge_kernel<<<2500, 256>>>(bg[l], srcA);
        srcA ^= 1;
    }
    // after 3 layers result is in g_hB (A->B->A->B)
    outmlp_kernel<<<(NN + 63) / 64, 64>>>(Wo1, bo1, Wo2, bo2, Wo3, bo3, out);
}